// round 9
// baseline (speedup 1.0000x reference)
#include <cuda_runtime.h>
#include <cuda_bf16.h>
#include <math.h>

#define Bn   8
#define An   1024
#define NNn  64
#define Gn   25
#define Fn   128
#define Ln   3
#define TBL  1024
#define RMAX 8.0f
#define CUTOFF_C 5.0f

#define NATOMS (Bn*An)          // 8192
#define NEDGES (Bn*An*NNn)      // 524288

// ---- scratch ----
__device__ float          g_x   [NATOMS*Fn];
__device__ __nv_bfloat16  g_yb  [NATOMS*Fn];
__device__ float          g_v   [NATOMS*Fn];
__device__ float          g_v2  [NATOMS*Fn];
__device__ float          g_r   [NEDGES];
__device__ float          g_tabf[Ln*TBL*Fn];
__device__ unsigned int   g_tab [Ln*TBL*Fn];   // packed (bf16 w[i], bf16 w[i+1])

__device__ __forceinline__ float sspf(float x){
    float ax = fabsf(x);
    return fmaxf(x, 0.0f) + log1pf(expf(-ax)) - 0.6931471805599453f;
}

// ---- packed f32x2 helpers (sm_103a) ----
__device__ __forceinline__ void fma2(unsigned long long &d, unsigned long long a, unsigned long long b){
    asm("fma.rn.f32x2 %0, %1, %2, %0;" : "+l"(d) : "l"(a), "l"(b));
}
__device__ __forceinline__ unsigned long long pack2(float lo, float hi){
    unsigned long long r; asm("mov.b64 %0, {%1, %2};" : "=l"(r) : "f"(lo), "f"(hi)); return r;
}
__device__ __forceinline__ float2 unpack2(unsigned long long v){
    float2 r; asm("mov.b64 {%0, %1}, %2;" : "=f"(r.x), "=f"(r.y) : "l"(v)); return r;
}
__device__ __forceinline__ float bf_lo(unsigned int u){ return __uint_as_float(u << 16); }
__device__ __forceinline__ float bf_hi(unsigned int u){ return __uint_as_float(u & 0xffff0000u); }

// ---------------- embedding ----------------
__global__ void embed_kernel(const int* __restrict__ z,
                             const float* __restrict__ emb,
                             float* __restrict__ x){
    int i = blockIdx.x*blockDim.x + threadIdx.x;
    if (i >= NATOMS*Fn) return;
    int ba = i >> 7;
    int f  = i & 127;
    x[i] = emb[z[ba]*Fn + f];
}

// ---------------- distances ----------------
__global__ void dist_kernel(const float* __restrict__ pos,
                            const float* __restrict__ cell,
                            const float* __restrict__ cell_off,
                            const int*   __restrict__ nbr,
                            float* __restrict__ r_out){
    int e = blockIdx.x*blockDim.x + threadIdx.x;
    if (e >= NEDGES) return;
    int a = (e / NNn) % An;
    int b =  e / (NNn*An);
    int j = nbr[e];
    const float* pi = pos + (b*An + a)*3;
    const float* pj = pos + (b*An + j)*3;
    const float* co = cell_off + (size_t)e*3;
    const float* cl = cell + b*9;
    float dx = pj[0]-pi[0] + co[0]*cl[0] + co[1]*cl[3] + co[2]*cl[6];
    float dy = pj[1]-pi[1] + co[0]*cl[1] + co[1]*cl[4] + co[2]*cl[7];
    float dz = pj[2]-pi[2] + co[0]*cl[2] + co[1]*cl[5] + co[2]*cl[8];
    float d2 = dx*dx + dy*dy + dz*dz;
    r_out[e] = (d2 > 0.0f) ? sqrtf(d2) : 0.0f;
}

// ---------------- filter table (fp32) ----------------
__global__ void table_kernel(const float* __restrict__ fw1,
                             const float* __restrict__ fb1,
                             const float* __restrict__ fw2,
                             const float* __restrict__ fb2,
                             float* __restrict__ tab){
    int l = blockIdx.x / TBL;
    int i = blockIdx.x % TBL;
    int t = threadIdx.x; // 128
    float r = (float)i * (RMAX / (float)(TBL-1));

    __shared__ float sf[Gn];
    __shared__ float sh[Fn];

    if (t < Gn){
        const float width = CUTOFF_C / (float)(Gn-1);
        const float coeff = -0.5f / (width*width);
        float d = r - (float)t * width;
        sf[t] = expf(coeff * d * d);
    }
    __syncthreads();

    float acc = fb1[l*Fn + t];
    #pragma unroll
    for (int g = 0; g < Gn; g++)
        acc = fmaf(sf[g], fw1[(l*Gn + g)*Fn + t], acc);
    sh[t] = sspf(acc);
    __syncthreads();

    float a2 = fb2[l*Fn + t];
    #pragma unroll 8
    for (int jj = 0; jj < Fn; jj++)
        a2 = fmaf(sh[jj], fw2[(l*Fn + jj)*Fn + t], a2);
    tab[((size_t)l*TBL + i)*Fn + t] = a2;
}

// ---------------- pack table: u32 = (bf16 w[i][f]) | (bf16 w[i+1][f] << 16) ----------------
__global__ void pack_kernel(const float* __restrict__ tabf,
                            unsigned int* __restrict__ tabp){
    int idx = blockIdx.x*blockDim.x + threadIdx.x;
    if (idx >= Ln*TBL*Fn) return;
    int f = idx & 127;
    int i = (idx >> 7) % TBL;
    int l = idx / (TBL*Fn);
    int i1 = (i+1 < TBL) ? i+1 : i;
    float w0 = tabf[idx];
    float w1 = tabf[((size_t)l*TBL + i1)*Fn + f];
    __nv_bfloat16 h0 = __float2bfloat16(w0);
    __nv_bfloat16 h1 = __float2bfloat16(w1);
    unsigned short b0 = *reinterpret_cast<unsigned short*>(&h0);
    unsigned short b1 = *reinterpret_cast<unsigned short*>(&h1);
    tabp[idx] = (unsigned int)b0 | ((unsigned int)b1 << 16);
}

// ---------------- edge aggregation ----------------
__global__ __launch_bounds__(128) void edge_kernel(
        const __nv_bfloat16* __restrict__ y,
        const int*   __restrict__ nbr,
        const float* __restrict__ r,
        const float* __restrict__ nmask,
        const unsigned int* __restrict__ tab,  // packed, this layer
        float* __restrict__ v){
    int ba = blockIdx.x;
    int b  = ba >> 10;
    int tid = threadIdx.x;
    int lane = tid & 31;
    int q    = tid >> 5;     // 0..3

    __shared__ int   s_j [NNn];
    __shared__ int   s_i0[NNn];
    __shared__ float s_c0[NNn];
    __shared__ float s_c1[NNn];
    __shared__ float sred[4*Fn];

    if (tid < NNn){
        int e = ba*NNn + tid;
        int j = __ldg(nbr + e);
        float rr = fminf(__ldg(r + e) * ((float)(TBL-1)/RMAX), (float)(TBL-1) - 1e-3f);
        int i0 = (int)rr;
        float fr = rr - (float)i0;
        float m = __ldg(nmask + e);
        s_j[tid]  = j;
        s_i0[tid] = i0;
        s_c0[tid] = m * (1.0f - fr);
        s_c1[tid] = m * fr;
    }
    __syncthreads();

    const uint4* tab4 = (const uint4*)tab;                          // row = 32 uint4
    const uint2* yb   = (const uint2*)(y + (size_t)b*An*Fn);        // row = 32 uint2

    float4 acc = make_float4(0.f,0.f,0.f,0.f);
    #pragma unroll 4
    for (int i = 0; i < 16; i++){
        int n = q*16 + i;
        int   j  = s_j[n];
        float c0 = s_c0[n];
        float c1 = s_c1[n];
        uint4 tp = tab4[s_i0[n]*32 + lane];
        uint2 yv = yb[j*32 + lane];
        float y0 = bf_lo(yv.x), y1 = bf_hi(yv.x);
        float y2 = bf_lo(yv.y), y3 = bf_hi(yv.y);
        acc.x = fmaf(fmaf(c1, bf_hi(tp.x), c0*bf_lo(tp.x)), y0, acc.x);
        acc.y = fmaf(fmaf(c1, bf_hi(tp.y), c0*bf_lo(tp.y)), y1, acc.y);
        acc.z = fmaf(fmaf(c1, bf_hi(tp.z), c0*bf_lo(tp.z)), y2, acc.z);
        acc.w = fmaf(fmaf(c1, bf_hi(tp.w), c0*bf_lo(tp.w)), y3, acc.w);
    }
    *(float4*)(sred + q*Fn + lane*4) = acc;
    __syncthreads();

    // tid = f
    float s = sred[tid] + sred[Fn + tid] + sred[2*Fn + tid] + sred[3*Fn + tid];
    v[(size_t)ba*Fn + tid] = s;
}

// ---------------- GEMM: C[M=8192,128] = op(A@W), f32x2 packed FFMA ----------------
// MODE 0: Cb = bf16(A@W)        (in2f -> y)
// MODE 1: C  = ssp(A@W + b)     (f2out)
// MODE 2: C  = A@W + b + res    (dense + residual)
#define APAD 68
template<int MODE>
__global__ __launch_bounds__(256) void gemm_kernel(
        const float* __restrict__ A,
        const float* __restrict__ W,
        const float* __restrict__ bias,
        const float* __restrict__ resid,
        void* __restrict__ Cout){
    extern __shared__ float smem[];
    float* Ws = smem;                 // 128*128
    float* As = smem + Fn*Fn;         // [k][m] padded APAD

    const int tid  = threadIdx.x;
    const int m0   = blockIdx.x * 64;
    const int trow = tid >> 4;        // 0..15
    const int tcol = tid & 15;        // 0..15

    // load W (float4) and A-tile (transposed)
    {
        const float4* W4 = (const float4*)W;
        float4* Ws4 = (float4*)Ws;
        #pragma unroll
        for (int i = 0; i < 16; i++)
            Ws4[tid + i*256] = W4[tid + i*256];
        #pragma unroll
        for (int i = 0; i < 32; i++){
            int idx = tid + i*256;
            int m = idx >> 7, k = idx & 127;
            As[k*APAD + m] = A[(size_t)(m0+m)*Fn + k];
        }
    }
    __syncthreads();

    unsigned long long acc2[4][4];
    #pragma unroll
    for (int i = 0; i < 4; i++)
        #pragma unroll
        for (int j = 0; j < 4; j++) acc2[i][j] = 0ULL;

    const float* asp = As + trow*4;
    const float* bsp = Ws + tcol*8;

    #pragma unroll 16
    for (int k = 0; k < Fn; k++){
        float4 av = *(const float4*)(asp + k*APAD);
        float4 b0 = *(const float4*)(bsp + k*Fn);
        float4 b1 = *(const float4*)(bsp + k*Fn + 4);
        unsigned long long bp0 = pack2(b0.x, b0.y);
        unsigned long long bp1 = pack2(b0.z, b0.w);
        unsigned long long bp2 = pack2(b1.x, b1.y);
        unsigned long long bp3 = pack2(b1.z, b1.w);
        unsigned long long ap0 = pack2(av.x, av.x);
        unsigned long long ap1 = pack2(av.y, av.y);
        unsigned long long ap2 = pack2(av.z, av.z);
        unsigned long long ap3 = pack2(av.w, av.w);
        fma2(acc2[0][0], ap0, bp0); fma2(acc2[0][1], ap0, bp1);
        fma2(acc2[0][2], ap0, bp2); fma2(acc2[0][3], ap0, bp3);
        fma2(acc2[1][0], ap1, bp0); fma2(acc2[1][1], ap1, bp1);
        fma2(acc2[1][2], ap1, bp2); fma2(acc2[1][3], ap1, bp3);
        fma2(acc2[2][0], ap2, bp0); fma2(acc2[2][1], ap2, bp1);
        fma2(acc2[2][2], ap2, bp2); fma2(acc2[2][3], ap2, bp3);
        fma2(acc2[3][0], ap3, bp0); fma2(acc2[3][1], ap3, bp1);
        fma2(acc2[3][2], ap3, bp2); fma2(acc2[3][3], ap3, bp3);
    }

    // epilogue
    if (MODE == 0){
        __nv_bfloat16* Cb = (__nv_bfloat16*)Cout;
        #pragma unroll
        for (int i = 0; i < 4; i++){
            size_t m = m0 + trow*4 + i;
            #pragma unroll
            for (int jp = 0; jp < 4; jp++){
                float2 p = unpack2(acc2[i][jp]);
                __nv_bfloat162 h = __floats2bfloat162_rn(p.x, p.y);
                *(__nv_bfloat162*)(Cb + m*Fn + tcol*8 + jp*2) = h;
            }
        }
    } else {
        float* C = (float*)Cout;
        float bv[8];
        #pragma unroll
        for (int j = 0; j < 8; j++) bv[j] = __ldg(bias + tcol*8 + j);
        #pragma unroll
        for (int i = 0; i < 4; i++){
            size_t m = m0 + trow*4 + i;
            #pragma unroll
            for (int jp = 0; jp < 4; jp++){
                float2 p = unpack2(acc2[i][jp]);
                float v0 = p.x + bv[jp*2];
                float v1 = p.y + bv[jp*2+1];
                if (MODE == 1){ v0 = sspf(v0); v1 = sspf(v1); }
                if (MODE == 2){
                    v0 += resid[m*Fn + tcol*8 + jp*2];
                    v1 += resid[m*Fn + tcol*8 + jp*2 + 1];
                }
                C[m*Fn + tcol*8 + jp*2]     = v0;
                C[m*Fn + tcol*8 + jp*2 + 1] = v1;
            }
        }
    }
}

#define GEMM_SMEM ((Fn*Fn + Fn*APAD)*4)

extern "C" void kernel_launch(void* const* d_in, const int* in_sizes, int n_in,
                              void* d_out, int out_size){
    const int*   zn       = (const int*)  d_in[0];
    const float* pos      = (const float*)d_in[1];
    const float* cell     = (const float*)d_in[2];
    const float* cell_off = (const float*)d_in[3];
    const int*   nbr      = (const int*)  d_in[4];
    const float* nmask    = (const float*)d_in[5];
    const float* emb      = (const float*)d_in[6];
    const float* fw1      = (const float*)d_in[7];
    const float* fb1      = (const float*)d_in[8];
    const float* fw2      = (const float*)d_in[9];
    const float* fb2      = (const float*)d_in[10];
    const float* in2f_w   = (const float*)d_in[11];
    const float* f2out_w  = (const float*)d_in[12];
    const float* f2out_b  = (const float*)d_in[13];
    const float* dense_w  = (const float*)d_in[14];
    const float* dense_b  = (const float*)d_in[15];
    float* out = (float*)d_out;

    float *px, *pv, *pv2, *pr, *ptabf;
    __nv_bfloat16* pyb;
    unsigned int* ptab;
    cudaGetSymbolAddress((void**)&px,    g_x);
    cudaGetSymbolAddress((void**)&pyb,   g_yb);
    cudaGetSymbolAddress((void**)&pv,    g_v);
    cudaGetSymbolAddress((void**)&pv2,   g_v2);
    cudaGetSymbolAddress((void**)&pr,    g_r);
    cudaGetSymbolAddress((void**)&ptabf, g_tabf);
    cudaGetSymbolAddress((void**)&ptab,  g_tab);

    cudaFuncSetAttribute(gemm_kernel<0>, cudaFuncAttributeMaxDynamicSharedMemorySize, GEMM_SMEM);
    cudaFuncSetAttribute(gemm_kernel<1>, cudaFuncAttributeMaxDynamicSharedMemorySize, GEMM_SMEM);
    cudaFuncSetAttribute(gemm_kernel<2>, cudaFuncAttributeMaxDynamicSharedMemorySize, GEMM_SMEM);

    embed_kernel<<<(NATOMS*Fn + 255)/256, 256>>>(zn, emb, px);
    dist_kernel <<<(NEDGES    + 255)/256, 256>>>(pos, cell, cell_off, nbr, pr);
    table_kernel<<<Ln*TBL, 128>>>(fw1, fb1, fw2, fb2, ptabf);
    pack_kernel <<<(Ln*TBL*Fn + 255)/256, 256>>>(ptabf, ptab);

    for (int l = 0; l < Ln; l++){
        gemm_kernel<0><<<NATOMS/64, 256, GEMM_SMEM>>>(px, in2f_w + (size_t)l*Fn*Fn,
                                                      nullptr, nullptr, pyb);
        edge_kernel<<<NATOMS, 128>>>(pyb, nbr, pr, nmask,
                                     ptab + (size_t)l*TBL*Fn, pv);
        gemm_kernel<1><<<NATOMS/64, 256, GEMM_SMEM>>>(pv, f2out_w + (size_t)l*Fn*Fn,
                                                      f2out_b + (size_t)l*Fn, nullptr, pv2);
        void* dst = (l == Ln-1) ? (void*)out : (void*)px;
        gemm_kernel<2><<<NATOMS/64, 256, GEMM_SMEM>>>(pv2, dense_w + (size_t)l*Fn*Fn,
                                                      dense_b + (size_t)l*Fn, px, dst);
    }
}

// round 14
// speedup vs baseline: 1.1066x; 1.1066x over previous
#include <cuda_runtime.h>
#include <cuda_bf16.h>
#include <math.h>

#define Bn   8
#define An   1024
#define NNn  64
#define Gn   25
#define Fn   128
#define Ln   3
#define TBL  1024
#define RMAX 8.0f
#define CUTOFF_C 5.0f
#define MAXZ 100

#define NATOMS (Bn*An)          // 8192
#define NEDGES (Bn*An*NNn)      // 524288

// ---- scratch ----
__device__ float          g_x   [NATOMS*Fn];
__device__ float          g_x2  [NATOMS*Fn];
__device__ __nv_bfloat16  g_yb  [NATOMS*Fn];
__device__ float          g_v   [NATOMS*Fn];
__device__ float          g_tabf[Ln*TBL*Fn];
__device__ unsigned int   g_tab [Ln*TBL*Fn];   // packed (bf16 w[i], bf16 w[i+1])
__device__ unsigned int   g_ji  [NEDGES];      // j | (i0<<16)
__device__ float2         g_cc  [NEDGES];      // (mask*(1-fr), mask*fr)
__device__ float          g_e2y [MAXZ*Fn];     // emb @ in2f_0

__device__ __forceinline__ float sspf(float x){
    float ax = fabsf(x);
    return fmaxf(x, 0.0f) + log1pf(expf(-ax)) - 0.6931471805599453f;
}

// ---- packed f32x2 helpers (sm_103a) ----
__device__ __forceinline__ void fma2(unsigned long long &d, unsigned long long a, unsigned long long b){
    asm("fma.rn.f32x2 %0, %1, %2, %0;" : "+l"(d) : "l"(a), "l"(b));
}
__device__ __forceinline__ unsigned long long pack2(float lo, float hi){
    unsigned long long r; asm("mov.b64 %0, {%1, %2};" : "=l"(r) : "f"(lo), "f"(hi)); return r;
}
__device__ __forceinline__ float2 unpack2(unsigned long long v){
    float2 r; asm("mov.b64 {%0, %1}, %2;" : "=f"(r.x), "=f"(r.y) : "l"(v)); return r;
}
__device__ __forceinline__ float bf_lo(unsigned int u){ return __uint_as_float(u << 16); }
__device__ __forceinline__ float bf_hi(unsigned int u){ return __uint_as_float(u & 0xffff0000u); }

// ---------------- emb2y: e2y[z,f] = sum_k emb[z,k]*in2f0[k,f] ----------------
__global__ void emb2y_kernel(const float* __restrict__ emb,
                             const float* __restrict__ in2f0,
                             float* __restrict__ e2y){
    int z = blockIdx.x;      // 0..MAXZ-1
    int f = threadIdx.x;     // 0..127
    __shared__ float se[Fn];
    se[f] = emb[z*Fn + f];
    __syncthreads();
    float acc = 0.0f;
    #pragma unroll 8
    for (int k = 0; k < Fn; k++)
        acc = fmaf(se[k], in2f0[k*Fn + f], acc);
    e2y[z*Fn + f] = acc;
}

// ---------------- embedding + y0 lookup ----------------
__global__ void embed_kernel(const int* __restrict__ z,
                             const float* __restrict__ emb,
                             const float* __restrict__ e2y,
                             float* __restrict__ x,
                             __nv_bfloat16* __restrict__ yb){
    int i = blockIdx.x*blockDim.x + threadIdx.x;   // NATOMS*64
    if (i >= NATOMS*64) return;
    int ba = i >> 6;
    int f2 = (i & 63)*2;
    int zz = z[ba];
    float2 xe = *(const float2*)(emb + zz*Fn + f2);
    float2 ye = *(const float2*)(e2y + zz*Fn + f2);
    *(float2*)(x + (size_t)ba*Fn + f2) = xe;
    *(__nv_bfloat162*)(yb + (size_t)ba*Fn + f2) = __floats2bfloat162_rn(ye.x, ye.y);
}

// ---------------- distances + edge prep ----------------
__global__ void dist_kernel(const float* __restrict__ pos,
                            const float* __restrict__ cell,
                            const float* __restrict__ cell_off,
                            const int*   __restrict__ nbr,
                            const float* __restrict__ nmask,
                            unsigned int* __restrict__ ji,
                            float2* __restrict__ cc){
    int e = blockIdx.x*blockDim.x + threadIdx.x;
    if (e >= NEDGES) return;
    int a = (e / NNn) % An;
    int b =  e / (NNn*An);
    int j = nbr[e];
    const float* pi = pos + (b*An + a)*3;
    const float* pj = pos + (b*An + j)*3;
    const float* co = cell_off + (size_t)e*3;
    const float* cl = cell + b*9;
    float dx = pj[0]-pi[0] + co[0]*cl[0] + co[1]*cl[3] + co[2]*cl[6];
    float dy = pj[1]-pi[1] + co[0]*cl[1] + co[1]*cl[4] + co[2]*cl[7];
    float dz = pj[2]-pi[2] + co[0]*cl[2] + co[1]*cl[5] + co[2]*cl[8];
    float d2 = dx*dx + dy*dy + dz*dz;
    float r  = (d2 > 0.0f) ? sqrtf(d2) : 0.0f;
    float rr = fminf(r * ((float)(TBL-1)/RMAX), (float)(TBL-1) - 1e-3f);
    int   i0 = (int)rr;
    float fr = rr - (float)i0;
    float m  = nmask[e];
    ji[e] = (unsigned int)j | ((unsigned int)i0 << 16);
    cc[e] = make_float2(m*(1.0f - fr), m*fr);
}

// ---------------- filter table (fp32) ----------------
__global__ void table_kernel(const float* __restrict__ fw1,
                             const float* __restrict__ fb1,
                             const float* __restrict__ fw2,
                             const float* __restrict__ fb2,
                             float* __restrict__ tab){
    int l = blockIdx.x / TBL;
    int i = blockIdx.x % TBL;
    int t = threadIdx.x; // 128
    float r = (float)i * (RMAX / (float)(TBL-1));

    __shared__ float sf[Gn];
    __shared__ float sh[Fn];

    if (t < Gn){
        const float width = CUTOFF_C / (float)(Gn-1);
        const float coeff = -0.5f / (width*width);
        float d = r - (float)t * width;
        sf[t] = expf(coeff * d * d);
    }
    __syncthreads();

    float acc = fb1[l*Fn + t];
    #pragma unroll
    for (int g = 0; g < Gn; g++)
        acc = fmaf(sf[g], fw1[(l*Gn + g)*Fn + t], acc);
    sh[t] = sspf(acc);
    __syncthreads();

    float a2 = fb2[l*Fn + t];
    #pragma unroll 8
    for (int jj = 0; jj < Fn; jj++)
        a2 = fmaf(sh[jj], fw2[(l*Fn + jj)*Fn + t], a2);
    tab[((size_t)l*TBL + i)*Fn + t] = a2;
}

// ---------------- pack table: u32 = (bf16 w[i][f]) | (bf16 w[i+1][f] << 16) ----------------
__global__ void pack_kernel(const float* __restrict__ tabf,
                            unsigned int* __restrict__ tabp){
    int idx = blockIdx.x*blockDim.x + threadIdx.x;
    if (idx >= Ln*TBL*Fn) return;
    int f = idx & 127;
    int i = (idx >> 7) % TBL;
    int l = idx / (TBL*Fn);
    int i1 = (i+1 < TBL) ? i+1 : i;
    float w0 = tabf[idx];
    float w1 = tabf[((size_t)l*TBL + i1)*Fn + f];
    __nv_bfloat16 h0 = __float2bfloat16(w0);
    __nv_bfloat16 h1 = __float2bfloat16(w1);
    unsigned short b0 = *reinterpret_cast<unsigned short*>(&h0);
    unsigned short b1 = *reinterpret_cast<unsigned short*>(&h1);
    tabp[idx] = (unsigned int)b0 | ((unsigned int)b1 << 16);
}

// ---------------- edge aggregation ----------------
__global__ __launch_bounds__(128) void edge_kernel(
        const __nv_bfloat16* __restrict__ y,
        const unsigned int* __restrict__ ji,
        const float2* __restrict__ cc,
        const unsigned int* __restrict__ tab,  // packed, this layer
        float* __restrict__ v){
    int ba = blockIdx.x;
    int b  = ba >> 10;
    int tid = threadIdx.x;
    int lane = tid & 31;
    int q    = tid >> 5;     // 0..3

    __shared__ int   s_j [NNn];
    __shared__ int   s_i0[NNn];
    __shared__ float s_c0[NNn];
    __shared__ float s_c1[NNn];
    __shared__ float sred[4*Fn];

    if (tid < NNn){
        int e = ba*NNn + tid;
        unsigned int p = __ldg(ji + e);
        float2 c = __ldg(cc + e);
        s_j [tid] = (int)(p & 0xffffu);
        s_i0[tid] = (int)(p >> 16);
        s_c0[tid] = c.x;
        s_c1[tid] = c.y;
    }
    __syncthreads();

    const uint4* tab4 = (const uint4*)tab;                          // row = 32 uint4
    const uint2* yb   = (const uint2*)(y + (size_t)b*An*Fn);        // row = 32 uint2

    float4 acc = make_float4(0.f,0.f,0.f,0.f);
    #pragma unroll 4
    for (int i = 0; i < 16; i++){
        int n = q*16 + i;
        int   j  = s_j[n];
        float c0 = s_c0[n];
        float c1 = s_c1[n];
        uint4 tp = tab4[s_i0[n]*32 + lane];
        uint2 yv = yb[j*32 + lane];
        float y0 = bf_lo(yv.x), y1 = bf_hi(yv.x);
        float y2 = bf_lo(yv.y), y3 = bf_hi(yv.y);
        acc.x = fmaf(fmaf(c1, bf_hi(tp.x), c0*bf_lo(tp.x)), y0, acc.x);
        acc.y = fmaf(fmaf(c1, bf_hi(tp.y), c0*bf_lo(tp.y)), y1, acc.y);
        acc.z = fmaf(fmaf(c1, bf_hi(tp.z), c0*bf_lo(tp.z)), y2, acc.z);
        acc.w = fmaf(fmaf(c1, bf_hi(tp.w), c0*bf_lo(tp.w)), y3, acc.w);
    }
    *(float4*)(sred + q*Fn + lane*4) = acc;
    __syncthreads();

    float s = sred[tid] + sred[Fn + tid] + sred[2*Fn + tid] + sred[3*Fn + tid];
    v[(size_t)ba*Fn + tid] = s;
}

// ---------------- fused layer-tail GEMM chain ----------------
// stage1: T1 = ssp(v@W1 + b1)
// stage2: xn = T1@W2 + b2 + x     -> xout
// stage3: ynext = bf16(xn@W3)     (skipped if LAST)
#define APAD 68

__device__ __forceinline__ void mm64(unsigned long long acc2[4][4],
                                     const float* asp, const float* bsp){
    #pragma unroll
    for (int i = 0; i < 4; i++)
        #pragma unroll
        for (int j = 0; j < 4; j++) acc2[i][j] = 0ULL;
    #pragma unroll 16
    for (int k = 0; k < Fn; k++){
        float4 av = *(const float4*)(asp + k*APAD);
        float4 b0 = *(const float4*)(bsp + k*Fn);
        float4 b1 = *(const float4*)(bsp + k*Fn + 4);
        unsigned long long bp0 = pack2(b0.x, b0.y);
        unsigned long long bp1 = pack2(b0.z, b0.w);
        unsigned long long bp2 = pack2(b1.x, b1.y);
        unsigned long long bp3 = pack2(b1.z, b1.w);
        unsigned long long ap0 = pack2(av.x, av.x);
        unsigned long long ap1 = pack2(av.y, av.y);
        unsigned long long ap2 = pack2(av.z, av.z);
        unsigned long long ap3 = pack2(av.w, av.w);
        fma2(acc2[0][0], ap0, bp0); fma2(acc2[0][1], ap0, bp1);
        fma2(acc2[0][2], ap0, bp2); fma2(acc2[0][3], ap0, bp3);
        fma2(acc2[1][0], ap1, bp0); fma2(acc2[1][1], ap1, bp1);
        fma2(acc2[1][2], ap1, bp2); fma2(acc2[1][3], ap1, bp3);
        fma2(acc2[2][0], ap2, bp0); fma2(acc2[2][1], ap2, bp1);
        fma2(acc2[2][2], ap2, bp2); fma2(acc2[2][3], ap2, bp3);
        fma2(acc2[3][0], ap3, bp0); fma2(acc2[3][1], ap3, bp1);
        fma2(acc2[3][2], ap3, bp2); fma2(acc2[3][3], ap3, bp3);
    }
}

__device__ __forceinline__ void loadW(const float* __restrict__ W, float* Ws, int tid){
    const float4* W4 = (const float4*)W;
    float4* Ws4 = (float4*)Ws;
    #pragma unroll
    for (int i = 0; i < 16; i++)
        Ws4[tid + i*256] = W4[tid + i*256];
}

template<bool LAST>
__global__ __launch_bounds__(256) void mega_kernel(
        const float* __restrict__ v,
        const float* x,                      // no restrict (residual source)
        const float* __restrict__ W1, const float* __restrict__ b1,
        const float* __restrict__ W2, const float* __restrict__ b2,
        const float* __restrict__ W3,
        float* xout,
        __nv_bfloat16* __restrict__ ynext){
    extern __shared__ float smem[];
    float* Ws = smem;                 // 128*128
    float* As = smem + Fn*Fn;         // [k][m], APAD

    const int tid  = threadIdx.x;
    const int m0   = blockIdx.x * 64;
    const int trow = tid >> 4;
    const int tcol = tid & 15;

    // prologue: v tile (transposed) + W1
    loadW(W1, Ws, tid);
    #pragma unroll
    for (int i = 0; i < 32; i++){
        int idx = tid + i*256;
        int m = idx >> 7, k = idx & 127;
        As[k*APAD + m] = v[(size_t)(m0+m)*Fn + k];
    }
    __syncthreads();

    unsigned long long acc2[4][4];
    const float* asp = As + trow*4;
    const float* bsp = Ws + tcol*8;

    // ---- stage 1 ----
    mm64(acc2, asp, bsp);
    __syncthreads();                      // all reads of As/Ws done

    #pragma unroll
    for (int i = 0; i < 4; i++){
        int m = trow*4 + i;
        #pragma unroll
        for (int jp = 0; jp < 4; jp++){
            int f = tcol*8 + jp*2;
            float2 p = unpack2(acc2[i][jp]);
            As[f*APAD + m]     = sspf(p.x + __ldg(b1 + f));
            As[(f+1)*APAD + m] = sspf(p.y + __ldg(b1 + f + 1));
        }
    }
    loadW(W2, Ws, tid);
    __syncthreads();

    // ---- stage 2 ----
    mm64(acc2, asp, bsp);
    __syncthreads();

    #pragma unroll
    for (int i = 0; i < 4; i++){
        int m = trow*4 + i;
        size_t gm = m0 + m;
        #pragma unroll
        for (int jp = 0; jp < 4; jp++){
            int f = tcol*8 + jp*2;
            float2 p = unpack2(acc2[i][jp]);
            float2 res = *(const float2*)(x + gm*Fn + f);
            float v0 = p.x + __ldg(b2 + f)     + res.x;
            float v1 = p.y + __ldg(b2 + f + 1) + res.y;
            *(float2*)(xout + gm*Fn + f) = make_float2(v0, v1);
            if (!LAST){
                As[f*APAD + m]     = v0;
                As[(f+1)*APAD + m] = v1;
            }
        }
    }

    // ---- stage 3 ----
    if (!LAST){
        loadW(W3, Ws, tid);
        __syncthreads();
        mm64(acc2, asp, bsp);
        #pragma unroll
        for (int i = 0; i < 4; i++){
            size_t gm = m0 + trow*4 + i;
            #pragma unroll
            for (int jp = 0; jp < 4; jp++){
                float2 p = unpack2(acc2[i][jp]);
                *(__nv_bfloat162*)(ynext + gm*Fn + tcol*8 + jp*2) =
                    __floats2bfloat162_rn(p.x, p.y);
            }
        }
    }
}

#define GEMM_SMEM ((Fn*Fn + Fn*APAD)*4)

extern "C" void kernel_launch(void* const* d_in, const int* in_sizes, int n_in,
                              void* d_out, int out_size){
    const int*   zn       = (const int*)  d_in[0];
    const float* pos      = (const float*)d_in[1];
    const float* cell     = (const float*)d_in[2];
    const float* cell_off = (const float*)d_in[3];
    const int*   nbr      = (const int*)  d_in[4];
    const float* nmask    = (const float*)d_in[5];
    const float* emb      = (const float*)d_in[6];
    const float* fw1      = (const float*)d_in[7];
    const float* fb1      = (const float*)d_in[8];
    const float* fw2      = (const float*)d_in[9];
    const float* fb2      = (const float*)d_in[10];
    const float* in2f_w   = (const float*)d_in[11];
    const float* f2out_w  = (const float*)d_in[12];
    const float* f2out_b  = (const float*)d_in[13];
    const float* dense_w  = (const float*)d_in[14];
    const float* dense_b  = (const float*)d_in[15];
    float* out = (float*)d_out;

    float *px, *px2, *pv, *ptabf, *pe2y;
    __nv_bfloat16* pyb;
    unsigned int *ptab, *pji;
    float2* pcc;
    cudaGetSymbolAddress((void**)&px,    g_x);
    cudaGetSymbolAddress((void**)&px2,   g_x2);
    cudaGetSymbolAddress((void**)&pyb,   g_yb);
    cudaGetSymbolAddress((void**)&pv,    g_v);
    cudaGetSymbolAddress((void**)&ptabf, g_tabf);
    cudaGetSymbolAddress((void**)&ptab,  g_tab);
    cudaGetSymbolAddress((void**)&pji,   g_ji);
    cudaGetSymbolAddress((void**)&pcc,   g_cc);
    cudaGetSymbolAddress((void**)&pe2y,  g_e2y);

    cudaFuncSetAttribute(mega_kernel<false>, cudaFuncAttributeMaxDynamicSharedMemorySize, GEMM_SMEM);
    cudaFuncSetAttribute(mega_kernel<true>,  cudaFuncAttributeMaxDynamicSharedMemorySize, GEMM_SMEM);

    // setup
    emb2y_kernel<<<MAXZ, 128>>>(emb, in2f_w, pe2y);
    embed_kernel<<<(NATOMS*64 + 255)/256, 256>>>(zn, emb, pe2y, px, pyb);
    dist_kernel <<<(NEDGES + 255)/256, 256>>>(pos, cell, cell_off, nbr, nmask, pji, pcc);
    table_kernel<<<Ln*TBL, 128>>>(fw1, fb1, fw2, fb2, ptabf);
    pack_kernel <<<(Ln*TBL*Fn + 255)/256, 256>>>(ptabf, ptab);

    // layers: x ping-pongs px -> px2 -> px; layer 2 writes d_out
    const float* xin[3]  = {px, px2, px};
    float*       xo [3]  = {px2, px, out};

    for (int l = 0; l < Ln; l++){
        edge_kernel<<<NATOMS, 128>>>(pyb, pji, pcc, ptab + (size_t)l*TBL*Fn, pv);
        if (l < Ln-1){
            mega_kernel<false><<<NATOMS/64, 256, GEMM_SMEM>>>(
                pv, xin[l],
                f2out_w + (size_t)l*Fn*Fn, f2out_b + (size_t)l*Fn,
                dense_w + (size_t)l*Fn*Fn, dense_b + (size_t)l*Fn,
                in2f_w + (size_t)(l+1)*Fn*Fn,
                xo[l], pyb);
        } else {
            mega_kernel<true><<<NATOMS/64, 256, GEMM_SMEM>>>(
                pv, xin[l],
                f2out_w + (size_t)l*Fn*Fn, f2out_b + (size_t)l*Fn,
                dense_w + (size_t)l*Fn*Fn, dense_b + (size_t)l*Fn,
                nullptr,
                xo[l], nullptr);
        }
    }
}